// round 2
// baseline (speedup 1.0000x reference)
#include <cuda_runtime.h>

#define NV 8000
#define NVT 20000
#define C_TOTAL 960
#define BATCH 8
#define P_TOTAL 4165

// Scratch (allocation-free rule: __device__ globals)
__device__ float g_rsel[(size_t)P_TOTAL * NV];   // gathered + leaky_relu'd rf, [sumP, 8000]
__device__ float g_wsel[(size_t)C_TOTAL * NV];   // gathered w, [960, 8000]
__device__ int   g_roi[NV];                      // normalized roi indices (int32)

// ---------------- packed f32x2 helpers (Blackwell) ----------------
#define FMA2(d, a, b, c) \
    asm("fma.rn.f32x2 %0, %1, %2, %3;" : "=l"(d) : "l"(a), "l"(b), "l"(c))
#define MUL2(d, a, b) \
    asm("mul.rn.f32x2 %0, %1, %2;" : "=l"(d) : "l"(a), "l"(b))
#define PACK2(d, x) \
    asm("mov.b64 %0, {%1, %1};" : "=l"(d) : "r"(x))

// ---------------- roi dtype normalization ----------------
// The reference declares roi_idx as int64, but JAX without x64 silently makes
// it int32. Detect on-device: an int64 buffer of values < 20000 has all-zero
// odd int32 words. Only reads the first 32KB (safe for either dtype).
__global__ void roi_norm_kernel(const int* __restrict__ r32) {
    bool is64 = true;
#pragma unroll
    for (int i = 1; i < 32; i += 2)
        if (r32[i] != 0) { is64 = false; break; }
    int idx = blockIdx.x * blockDim.x + threadIdx.x;
    if (idx < NV) g_roi[idx] = is64 ? r32[2 * idx] : r32[idx];
}

// ---------------- gather kernels ----------------
__global__ void gather_r_kernel(const float* __restrict__ rf,
                                int P, int pOff) {
    long long idx = (long long)blockIdx.x * blockDim.x + threadIdx.x;
    long long total = (long long)P * NV;
    if (idx >= total) return;
    int v = (int)(idx % NV);
    int p = (int)(idx / NV);
    float x = rf[(size_t)p * NVT + (size_t)g_roi[v]];
    g_rsel[(size_t)(pOff + p) * NV + v] = (x > 0.0f) ? x : 0.01f * x;
}

__global__ void gather_w_kernel(const float* __restrict__ w,
                                int Cn, int cOff) {
    long long idx = (long long)blockIdx.x * blockDim.x + threadIdx.x;
    long long total = (long long)Cn * NV;
    if (idx >= total) return;
    int v = (int)(idx % NV);
    int c = (int)(idx / NV);
    g_wsel[(size_t)(cOff + c) * NV + v] = w[(size_t)c * NVT + (size_t)g_roi[v]];
}

// ---------------- GEMM: out[b, cOff+c, v] = (A @ rsel)[m, v] * wsel[cOff+c, v] ----------------
// A: [M, K] row-major (fmap reshaped, M = B*Cn), rsel slice: [K, 8000] row-major.
#define BM 128
#define BN 128
#define BK 16

__global__ void __launch_bounds__(256, 2)
gemm_layer(const float* __restrict__ A, float* __restrict__ out,
           int M, int K, int pOff, int Cn, int cOff)
{
    __shared__ float As[BK][BM + 4];   // transposed A tile, padded vs STS conflicts
    __shared__ float Bs[BK][BN];

    const float* __restrict__ Bm = g_rsel + (size_t)pOff * NV;

    const int tid = threadIdx.x;
    const int bn = blockIdx.x * BN;   // v tile
    const int bm = blockIdx.y * BM;   // row tile
    const int tx = tid & 15;          // -> n
    const int ty = tid >> 4;          // -> m

    unsigned long long acc[8][4];
#pragma unroll
    for (int r = 0; r < 8; r++)
#pragma unroll
        for (int j = 0; j < 4; j++) acc[r][j] = 0ULL;

    const int nkt = (K + BK - 1) / BK;
    for (int kt = 0; kt < nkt; kt++) {
        const int k0 = kt * BK;

        // A tile: 2048 scalars, 8 per thread
#pragma unroll
        for (int i = 0; i < 8; i++) {
            int e  = i * 256 + tid;
            int m  = e >> 4;
            int kk = e & 15;
            int kg = k0 + kk;
            float val = (kg < K) ? A[(size_t)(bm + m) * K + kg] : 0.0f;
            As[kk][m] = val;
        }
        // B tile: 512 float4, 2 per thread, fully coalesced
#pragma unroll
        for (int i = 0; i < 2; i++) {
            int e  = i * 256 + tid;
            int kk = e >> 5;
            int c4 = e & 31;
            int kg = k0 + kk;
            int vg = bn + c4 * 4;
            float4 val = make_float4(0.f, 0.f, 0.f, 0.f);
            if (kg < K && vg < NV)
                val = *(const float4*)&Bm[(size_t)kg * NV + vg];
            *(float4*)&Bs[kk][c4 * 4] = val;
        }
        __syncthreads();

#pragma unroll
        for (int k = 0; k < BK; k++) {
            float4 a0 = *(const float4*)&As[k][ty * 8];
            float4 a1 = *(const float4*)&As[k][ty * 8 + 4];
            const ulonglong2* bp = (const ulonglong2*)&Bs[k][tx * 8];
            ulonglong2 bA = bp[0];
            ulonglong2 bB = bp[1];
            unsigned long long b0 = bA.x, b1 = bA.y, b2 = bB.x, b3 = bB.y;

            float a[8] = {a0.x, a0.y, a0.z, a0.w, a1.x, a1.y, a1.z, a1.w};
#pragma unroll
            for (int r = 0; r < 8; r++) {
                unsigned long long ad;
                PACK2(ad, __float_as_uint(a[r]));
                FMA2(acc[r][0], ad, b0, acc[r][0]);
                FMA2(acc[r][1], ad, b1, acc[r][1]);
                FMA2(acc[r][2], ad, b2, acc[r][2]);
                FMA2(acc[r][3], ad, b3, acc[r][3]);
            }
        }
        __syncthreads();
    }

    // Epilogue: scale by gathered w, scatter into [B, 960, 8000]
    const int vbase = bn + tx * 8;
#pragma unroll
    for (int r = 0; r < 8; r++) {
        int m = bm + ty * 8 + r;
        int bIdx = m / Cn;
        int c = m - bIdx * Cn;
        size_t orow = ((size_t)bIdx * C_TOTAL + cOff + c) * NV;
        size_t wrow = (size_t)(cOff + c) * NV;
#pragma unroll
        for (int j = 0; j < 4; j++) {
            int v = vbase + j * 2;
            if (v < NV) {
                unsigned long long wpair =
                    *(const unsigned long long*)&g_wsel[wrow + v];
                unsigned long long res;
                MUL2(res, acc[r][j], wpair);
                *(unsigned long long*)&out[orow + v] = res;
            }
        }
    }
}

// ---------------- launch ----------------
extern "C" void kernel_launch(void* const* d_in, const int* in_sizes, int n_in,
                              void* d_out, int out_size) {
    // Identify inputs by element count (all 13 sizes distinct -> robust to metadata order)
    static const int fsz[4] = {1605632, 802816, 401408, 200704};       // 8*C*h*h
    static const int rsz[4] = {62720000, 15680000, 3920000, 980000};   // h*h*20000
    static const int wsz[4] = {1280000, 2560000, 5120000, 10240000};   // C*20000

    const float* fmap[4] = {0, 0, 0, 0};
    const float* rfp[4]  = {0, 0, 0, 0};
    const float* wptr[4] = {0, 0, 0, 0};
    const void*  roi = 0;

    for (int i = 0; i < n_in; i++) {
        int s = in_sizes[i];
        if (s == NV) { roi = d_in[i]; continue; }
        for (int l = 0; l < 4; l++) {
            if (s == fsz[l]) fmap[l] = (const float*)d_in[i];
            else if (s == rsz[l]) rfp[l]  = (const float*)d_in[i];
            else if (s == wsz[l]) wptr[l] = (const float*)d_in[i];
        }
    }

    static const int Ps[4] = {3136, 784, 196, 49};
    static const int Po[4] = {0, 3136, 3920, 4116};
    static const int Cs[4] = {64, 128, 256, 512};
    static const int Co[4] = {0, 64, 192, 448};

    float* out = (float*)d_out;

    // Normalize roi dtype first
    roi_norm_kernel<<<(NV + 255) / 256, 256>>>((const int*)roi);

    // Gather passes
    for (int l = 0; l < 4; l++) {
        long long tr = (long long)Ps[l] * NV;
        gather_r_kernel<<<(unsigned)((tr + 255) / 256), 256>>>(rfp[l], Ps[l], Po[l]);
        long long tw = (long long)Cs[l] * NV;
        gather_w_kernel<<<(unsigned)((tw + 255) / 256), 256>>>(wptr[l], Cs[l], Co[l]);
    }

    // GEMMs (depend on gathers; same stream -> ordered)
    for (int l = 0; l < 4; l++) {
        int M = BATCH * Cs[l];
        dim3 grid((NV + BN - 1) / BN, M / BM);
        gemm_layer<<<grid, 256>>>(fmap[l], out, M, Ps[l], Po[l], Cs[l], Co[l]);
    }
}

// round 4
// speedup vs baseline: 2.0700x; 2.0700x over previous
#include <cuda_runtime.h>
#include <cuda_bf16.h>
#include <cstdint>

#define NV 8000
#define NVT 20000
#define C_TOTAL 960

// Layer geometry (Kpad = K rounded up to 32)
//   l:      0      1      2      3
//   C:     64    128    256    512     (M = 8*C)
//   K:   3136    784    196     49
//   Kp:  3136    800    224     64
#define KPAD_SUM 4224
#define A_ELEMS 3145728   // sum M*Kpad

// ---------------- scratch (__device__ globals; allocation-free rule) ----------------
__device__ __align__(16) __nv_bfloat16 g_ahi[A_ELEMS];
__device__ __align__(16) __nv_bfloat16 g_alo[A_ELEMS];
__device__ __align__(16) __nv_bfloat16 g_bhi[(size_t)NV * KPAD_SUM];  // [8000, Kp] K-major
__device__ __align__(16) __nv_bfloat16 g_blo[(size_t)NV * KPAD_SUM];
__device__ __align__(16) float g_wsel[(size_t)C_TOTAL * NV];
__device__ int g_roi[NV];

// ---------------- prep kernels ----------------
// roi dtype normalization (reference says int64; JAX x64-off gives int32).
__global__ void roi_norm_kernel(const int* __restrict__ r32) {
    bool is64 = true;
#pragma unroll
    for (int i = 1; i < 32; i += 2)
        if (r32[i] != 0) { is64 = false; break; }
    int idx = blockIdx.x * blockDim.x + threadIdx.x;
    if (idx < NV) g_roi[idx] = is64 ? r32[2 * idx] : r32[idx];
}

// fmap [M,K] fp32 -> g_ahi/g_alo [M,Kpad] bf16 (hi + residual), zero-padded
__global__ void split_fmap_kernel(const float* __restrict__ f, int M, int K, int Kpad,
                                  size_t aOff) {
    int idx = blockIdx.x * blockDim.x + threadIdx.x;
    if (idx >= M * Kpad) return;
    int m = idx / Kpad, k = idx - m * Kpad;
    float x = (k < K) ? f[(size_t)m * K + k] : 0.0f;
    __nv_bfloat16 hi = __float2bfloat16(x);
    __nv_bfloat16 lo = __float2bfloat16(x - __bfloat162float(hi));
    g_ahi[aOff + idx] = hi;
    g_alo[aOff + idx] = lo;
}

// rf [K, 20000] -> g_bhi/g_blo [8000, Kpad] (gather + leaky_relu + transpose + split)
__global__ void gather_tr_kernel(const float* __restrict__ rf, int K, int Kpad, size_t bOff) {
    __shared__ float tile[32][257];
    const int tid = threadIdx.x;
    const int p0 = blockIdx.x * 32;
    const int v0 = blockIdx.y * 256;

    int vr = v0 + tid;
    int ri = (vr < NV) ? g_roi[vr] : 0;
#pragma unroll 4
    for (int i = 0; i < 32; i++) {
        int p = p0 + i;
        float x = 0.0f;
        if (p < K && vr < NV) {
            x = rf[(size_t)p * NVT + ri];
            x = (x > 0.0f) ? x : 0.01f * x;
        }
        tile[i][tid] = x;
    }
    __syncthreads();

    const int pl = tid & 31;
    const int vb = tid >> 5;
#pragma unroll 4
    for (int i = 0; i < 32; i++) {
        int vloc = vb + (i << 3);
        int v = v0 + vloc;
        if (v < NV) {
            float x = tile[pl][vloc];
            __nv_bfloat16 hi = __float2bfloat16(x);
            __nv_bfloat16 lo = __float2bfloat16(x - __bfloat162float(hi));
            size_t o = bOff + (size_t)v * Kpad + p0 + pl;
            g_bhi[o] = hi;
            g_blo[o] = lo;
        }
    }
}

__global__ void gather_w_kernel(const float* __restrict__ w, int Cn, int cOff) {
    long long idx = (long long)blockIdx.x * blockDim.x + threadIdx.x;
    if (idx >= (long long)Cn * NV) return;
    int v = (int)(idx % NV);
    int c = (int)(idx / NV);
    g_wsel[(size_t)(cOff + c) * NV + v] = w[(size_t)c * NVT + (size_t)g_roi[v]];
}

// ---------------- mma.sync GEMM ----------------
// out[b, cOff+c, v] = (A @ B^T)[m, v] * wsel ; A [M,Kp] bf16 hi/lo, B [8000,Kp] bf16 hi/lo.
// BM=128, BN=128, BK=32; 8 warps, each 64(m) x 32(n); 3-stage cp.async pipeline.

#define STAGE_BYTES 32768
#define A_HI_OFF 0
#define A_LO_OFF 8192
#define B_HI_OFF 16384
#define B_LO_OFF 24576
#define SMEM_TOTAL (3 * STAGE_BYTES)

__device__ __forceinline__ uint32_t smem_u32(const void* p) {
    uint32_t a;
    asm("{ .reg .u64 t; cvta.to.shared.u64 t, %1; cvt.u32.u64 %0, t; }" : "=r"(a) : "l"(p));
    return a;
}
// 64B rows (32 bf16); chunk = 16B unit. Swizzle keeps ldmatrix conflict-free.
__device__ __forceinline__ uint32_t swz(uint32_t base, int row, int chunk) {
    return base + (uint32_t)(row * 64 + (chunk ^ ((row >> 1) & 3)) * 16);
}
__device__ __forceinline__ void cp16(uint32_t dst, const void* src, bool v) {
    asm volatile("cp.async.cg.shared.global [%0], [%1], 16, %2;"
                 :: "r"(dst), "l"(src), "r"(v ? 16 : 0));
}
#define CP_COMMIT() asm volatile("cp.async.commit_group;" ::: "memory")
#define CP_WAIT1()  asm volatile("cp.async.wait_group 1;" ::: "memory")

#define LDSM4(r0, r1, r2, r3, a) \
    asm volatile("ldmatrix.sync.aligned.m8n8.x4.shared.b16 {%0,%1,%2,%3}, [%4];" \
                 : "=r"(r0), "=r"(r1), "=r"(r2), "=r"(r3) : "r"(a))

#define MMA(d, a, b0_, b1_) \
    asm volatile("mma.sync.aligned.m16n8k16.row.col.f32.bf16.bf16.f32 " \
                 "{%0,%1,%2,%3}, {%4,%5,%6,%7}, {%8,%9}, {%0,%1,%2,%3};" \
                 : "+f"((d)[0]), "+f"((d)[1]), "+f"((d)[2]), "+f"((d)[3]) \
                 : "r"((a)[0]), "r"((a)[1]), "r"((a)[2]), "r"((a)[3]), "r"(b0_), "r"(b1_))

__global__ void __launch_bounds__(256)
gemm_mma(size_t aOff, size_t bOff, int Kpad, int cShift, int cOff, float* __restrict__ out)
{
    extern __shared__ char smem[];
    const uint32_t sb = smem_u32(smem);
    const int tid = threadIdx.x;
    const int lane = tid & 31;
    const int w = tid >> 5;
    const int wm = w >> 2;          // 0..1
    const int wn = w & 3;           // 0..3
    const int bm = blockIdx.x * 128;
    const int bn = blockIdx.y * 128;

    const __nv_bfloat16* __restrict__ Ahi = g_ahi + aOff;
    const __nv_bfloat16* __restrict__ Alo = g_alo + aOff;
    const __nv_bfloat16* __restrict__ Bhi = g_bhi + bOff;
    const __nv_bfloat16* __restrict__ Blo = g_blo + bOff;

    const int nkt = Kpad >> 5;

    // ---- stage loader: 2048 x 16B chunks, 8 per thread ----
    auto load_stage = [&](int kt, int buf) {
        const uint32_t s = sb + buf * STAGE_BYTES;
        const int k0 = kt << 5;
#pragma unroll
        for (int half = 0; half < 2; half++) {
            int cid = half * 256 + tid;
            int row = cid >> 2, ch = cid & 3;
            size_t ga = (size_t)(bm + row) * Kpad + k0 + ch * 8;
            cp16(swz(s + A_HI_OFF, row, ch), Ahi + ga, true);
            cp16(swz(s + A_LO_OFF, row, ch), Alo + ga, true);
            int n = bn + row;
            bool v = n < NV;
            size_t gb = v ? ((size_t)n * Kpad + k0 + ch * 8) : 0;
            cp16(swz(s + B_HI_OFF, row, ch), Bhi + gb, v);
            cp16(swz(s + B_LO_OFF, row, ch), Blo + gb, v);
        }
    };

    float acc[4][4][4];
#pragma unroll
    for (int i = 0; i < 4; i++)
#pragma unroll
        for (int j = 0; j < 4; j++)
#pragma unroll
            for (int q = 0; q < 4; q++) acc[i][j][q] = 0.0f;

    // prologue
    load_stage(0, 0); CP_COMMIT();
    if (nkt > 1) load_stage(1, 1);
    CP_COMMIT();

    const int mid = lane >> 3, r8 = lane & 7;

    for (int kt = 0; kt < nkt; kt++) {
        CP_WAIT1();
        __syncthreads();
        if (kt + 2 < nkt) load_stage(kt + 2, (kt + 2) % 3);
        CP_COMMIT();

        const uint32_t s = sb + (kt % 3) * STAGE_BYTES;
#pragma unroll
        for (int ks = 0; ks < 2; ks++) {
            uint32_t ah[4][4], al[4][4], bh[2][4], bl[2][4];
            // A frags: row = wm*64 + mi*16 + (mid&1)*8 + r8 ; chunk = ks*2 + (mid>>1)
            int arow = wm * 64 + (mid & 1) * 8 + r8;
            int ach = ks * 2 + (mid >> 1);
#pragma unroll
            for (int mi = 0; mi < 4; mi++) {
                LDSM4(ah[mi][0], ah[mi][1], ah[mi][2], ah[mi][3], swz(s + A_HI_OFF, arow + mi * 16, ach));
                LDSM4(al[mi][0], al[mi][1], al[mi][2], al[mi][3], swz(s + A_LO_OFF, arow + mi * 16, ach));
            }
            // B frags: row(n) = wn*32 + nj*16 + (mid>>1)*8 + r8 ; chunk = ks*2 + (mid&1)
            int brow = wn * 32 + (mid >> 1) * 8 + r8;
            int bch = ks * 2 + (mid & 1);
#pragma unroll
            for (int nj = 0; nj < 2; nj++) {
                LDSM4(bh[nj][0], bh[nj][1], bh[nj][2], bh[nj][3], swz(s + B_HI_OFF, brow + nj * 16, bch));
                LDSM4(bl[nj][0], bl[nj][1], bl[nj][2], bl[nj][3], swz(s + B_LO_OFF, brow + nj * 16, bch));
            }
#pragma unroll
            for (int mi = 0; mi < 4; mi++) {
#pragma unroll
                for (int ni = 0; ni < 4; ni++) {
                    uint32_t* bph = &bh[ni >> 1][(ni & 1) * 2];
                    uint32_t* bpl = &bl[ni >> 1][(ni & 1) * 2];
                    MMA(acc[mi][ni], ah[mi], bph[0], bph[1]);
                    MMA(acc[mi][ni], ah[mi], bpl[0], bpl[1]);
                    MMA(acc[mi][ni], al[mi], bph[0], bph[1]);
                }
            }
        }
        __syncthreads();
    }

    // ---- epilogue: scale by wsel, store ----
    const int tg = lane >> 2, tq = lane & 3;
    const int Cm1 = (1 << cShift) - 1;
#pragma unroll
    for (int mi = 0; mi < 4; mi++) {
#pragma unroll
        for (int h = 0; h < 2; h++) {
            int m = bm + wm * 64 + mi * 16 + h * 8 + tg;
            int bI = m >> cShift;
            int c = m & Cm1;
            float* orow = out + ((size_t)bI * C_TOTAL + cOff + c) * NV;
            const float* wrow = g_wsel + (size_t)(cOff + c) * NV;
#pragma unroll
            for (int ni = 0; ni < 4; ni++) {
                int col = bn + wn * 32 + ni * 8 + tq * 2;
                if (col < NV) {
                    float2 wv = *(const float2*)(wrow + col);
                    float2 o;
                    o.x = acc[mi][ni][h * 2 + 0] * wv.x;
                    o.y = acc[mi][ni][h * 2 + 1] * wv.y;
                    *(float2*)(orow + col) = o;
                }
            }
        }
    }
}

// ---------------- launch ----------------
extern "C" void kernel_launch(void* const* d_in, const int* in_sizes, int n_in,
                              void* d_out, int out_size) {
    static const int fsz[4] = {1605632, 802816, 401408, 200704};
    static const int rsz[4] = {62720000, 15680000, 3920000, 980000};
    static const int wsz[4] = {1280000, 2560000, 5120000, 10240000};

    const float* fmap[4] = {0, 0, 0, 0};
    const float* rfp[4]  = {0, 0, 0, 0};
    const float* wptr[4] = {0, 0, 0, 0};
    const void*  roi = 0;

    for (int i = 0; i < n_in; i++) {
        int s = in_sizes[i];
        if (s == NV) { roi = d_in[i]; continue; }
        for (int l = 0; l < 4; l++) {
            if (s == fsz[l]) fmap[l] = (const float*)d_in[i];
            else if (s == rsz[l]) rfp[l]  = (const float*)d_in[i];
            else if (s == wsz[l]) wptr[l] = (const float*)d_in[i];
        }
    }

    static const int    Ks[4]  = {3136, 784, 196, 49};
    static const int    Kp[4]  = {3136, 800, 224, 64};
    static const size_t aOf[4] = {0, 1605632, 2424832, 2883584};
    static const size_t bOf[4] = {0, 25088000, 31488000, 33280000};
    static const int    Cs[4]  = {64, 128, 256, 512};
    static const int    Csh[4] = {6, 7, 8, 9};
    static const int    Co[4]  = {0, 64, 192, 448};

    float* out = (float*)d_out;

    roi_norm_kernel<<<(NV + 255) / 256, 256>>>((const int*)roi);

    for (int l = 0; l < 4; l++) {
        int M = 8 * Cs[l];
        int n = M * Kp[l];
        split_fmap_kernel<<<(n + 255) / 256, 256>>>(fmap[l], M, Ks[l], Kp[l], aOf[l]);
        gather_tr_kernel<<<dim3(Kp[l] / 32, 32), 256>>>(rfp[l], Ks[l], Kp[l], bOf[l]);
        long long tw = (long long)Cs[l] * NV;
        gather_w_kernel<<<(unsigned)((tw + 255) / 256), 256>>>(wptr[l], Cs[l], Co[l]);
    }

    cudaFuncSetAttribute(gemm_mma, cudaFuncAttributeMaxDynamicSharedMemorySize, SMEM_TOTAL);
    for (int l = 0; l < 4; l++) {
        int M = 8 * Cs[l];
        dim3 grid(M / 128, (NV + 127) / 128);   // m fastest -> B n-tile L2 reuse
        gemm_mma<<<grid, 256, SMEM_TOTAL>>>(aOf[l], bOf[l], Kp[l], Csh[l], Co[l], out);
    }
}

// round 5
// speedup vs baseline: 2.1071x; 1.0179x over previous
#include <cuda_runtime.h>
#include <cuda_bf16.h>
#include <cstdint>

#define NV 8000
#define NVT 20000
#define C_TOTAL 960

// Layer geometry (Kpad = K rounded up to 32)
//   l:      0      1      2      3
//   C:     64    128    256    512     (M = 8*C)
//   K:   3136    784    196     49
//   Kp:  3136    800    224     64
#define KPAD_SUM 4224
#define A_ELEMS 3145728   // sum M*Kpad

// ---------------- scratch (__device__ globals; allocation-free rule) ----------------
__device__ __align__(16) __nv_bfloat16 g_ahi[A_ELEMS];
__device__ __align__(16) __nv_bfloat16 g_alo[A_ELEMS];
__device__ __align__(16) __nv_bfloat16 g_bhi[(size_t)NV * KPAD_SUM];  // [8000, Kp] K-major
__device__ __align__(16) __nv_bfloat16 g_blo[(size_t)NV * KPAD_SUM];
__device__ __align__(16) float g_wsel[(size_t)C_TOTAL * NV];
__device__ int g_roi[NV];

// ---------------- prep kernels ----------------
// roi dtype normalization (reference says int64; JAX x64-off gives int32).
__global__ void roi_norm_kernel(const int* __restrict__ r32) {
    bool is64 = true;
#pragma unroll
    for (int i = 1; i < 32; i += 2)
        if (r32[i] != 0) { is64 = false; break; }
    int idx = blockIdx.x * blockDim.x + threadIdx.x;
    if (idx < NV) g_roi[idx] = is64 ? r32[2 * idx] : r32[idx];
}

// fmap [M,K] fp32 -> g_ahi/g_alo [M,Kpad] bf16 (hi + residual), zero-padded
__global__ void split_fmap_kernel(const float* __restrict__ f, int M, int K, int Kpad,
                                  size_t aOff) {
    int idx = blockIdx.x * blockDim.x + threadIdx.x;
    if (idx >= M * Kpad) return;
    int m = idx / Kpad, k = idx - m * Kpad;
    float x = (k < K) ? f[(size_t)m * K + k] : 0.0f;
    __nv_bfloat16 hi = __float2bfloat16(x);
    __nv_bfloat16 lo = __float2bfloat16(x - __bfloat162float(hi));
    g_ahi[aOff + idx] = hi;
    g_alo[aOff + idx] = lo;
}

// rf [K, 20000] -> g_bhi/g_blo [8000, Kpad] (gather + leaky_relu + transpose + split)
__global__ void gather_tr_kernel(const float* __restrict__ rf, int K, int Kpad, size_t bOff) {
    __shared__ float tile[32][257];
    const int tid = threadIdx.x;
    const int p0 = blockIdx.x * 32;
    const int v0 = blockIdx.y * 256;

    int vr = v0 + tid;
    int ri = (vr < NV) ? g_roi[vr] : 0;
#pragma unroll 4
    for (int i = 0; i < 32; i++) {
        int p = p0 + i;
        float x = 0.0f;
        if (p < K && vr < NV) {
            x = rf[(size_t)p * NVT + ri];
            x = (x > 0.0f) ? x : 0.01f * x;
        }
        tile[i][tid] = x;
    }
    __syncthreads();

    const int pl = tid & 31;
    const int vb = tid >> 5;
#pragma unroll 4
    for (int i = 0; i < 32; i++) {
        int vloc = vb + (i << 3);
        int v = v0 + vloc;
        if (v < NV) {
            float x = tile[pl][vloc];
            __nv_bfloat16 hi = __float2bfloat16(x);
            __nv_bfloat16 lo = __float2bfloat16(x - __bfloat162float(hi));
            size_t o = bOff + (size_t)v * Kpad + p0 + pl;
            g_bhi[o] = hi;
            g_blo[o] = lo;
        }
    }
}

__global__ void gather_w_kernel(const float* __restrict__ w, int Cn, int cOff) {
    long long idx = (long long)blockIdx.x * blockDim.x + threadIdx.x;
    if (idx >= (long long)Cn * NV) return;
    int v = (int)(idx % NV);
    int c = (int)(idx / NV);
    g_wsel[(size_t)(cOff + c) * NV + v] = w[(size_t)c * NVT + (size_t)g_roi[v]];
}

// ---------------- mma.sync GEMM ----------------
// out[b, cOff+c, v] = (A @ B^T)[m, v] * wsel ; A [M,Kp] bf16 hi/lo, B [8000,Kp] bf16 hi/lo.
// BM=128, BN=128, BK=32; 8 warps, each 64(m) x 32(n); 3-stage cp.async pipeline.

#define STAGE_BYTES 32768
#define A_HI_OFF 0
#define A_LO_OFF 8192
#define B_HI_OFF 16384
#define B_LO_OFF 24576
#define SMEM_TOTAL (3 * STAGE_BYTES)

__device__ __forceinline__ uint32_t smem_u32(const void* p) {
    uint32_t a;
    asm("{ .reg .u64 t; cvta.to.shared.u64 t, %1; cvt.u32.u64 %0, t; }" : "=r"(a) : "l"(p));
    return a;
}
// 64B rows (32 bf16); chunk = 16B unit. Swizzle keeps ldmatrix conflict-free.
__device__ __forceinline__ uint32_t swz(uint32_t base, int row, int chunk) {
    return base + (uint32_t)(row * 64 + (chunk ^ ((row >> 1) & 3)) * 16);
}
__device__ __forceinline__ void cp16(uint32_t dst, const void* src, bool v) {
    asm volatile("cp.async.cg.shared.global [%0], [%1], 16, %2;"
                 :: "r"(dst), "l"(src), "r"(v ? 16 : 0));
}
#define CP_COMMIT() asm volatile("cp.async.commit_group;" ::: "memory")
#define CP_WAIT1()  asm volatile("cp.async.wait_group 1;" ::: "memory")

#define LDSM4(r0, r1, r2, r3, a) \
    asm volatile("ldmatrix.sync.aligned.m8n8.x4.shared.b16 {%0,%1,%2,%3}, [%4];" \
                 : "=r"(r0), "=r"(r1), "=r"(r2), "=r"(r3) : "r"(a))

#define MMA(d, a, b0_, b1_) \
    asm volatile("mma.sync.aligned.m16n8k16.row.col.f32.bf16.bf16.f32 " \
                 "{%0,%1,%2,%3}, {%4,%5,%6,%7}, {%8,%9}, {%0,%1,%2,%3};" \
                 : "+f"((d)[0]), "+f"((d)[1]), "+f"((d)[2]), "+f"((d)[3]) \
                 : "r"((a)[0]), "r"((a)[1]), "r"((a)[2]), "r"((a)[3]), "r"(b0_), "r"(b1_))

__global__ void __launch_bounds__(256, 2)
gemm_mma(size_t aOff, size_t bOff, int Kpad, int cShift, int cOff, float* __restrict__ out)
{
    extern __shared__ char smem[];
    const uint32_t sb = smem_u32(smem);
    const int tid = threadIdx.x;
    const int lane = tid & 31;
    const int w = tid >> 5;
    const int wm = w >> 2;          // 0..1
    const int wn = w & 3;           // 0..3
    const int bm = blockIdx.x * 128;
    const int bn = blockIdx.y * 128;

    const __nv_bfloat16* __restrict__ Ahi = g_ahi + aOff;
    const __nv_bfloat16* __restrict__ Alo = g_alo + aOff;
    const __nv_bfloat16* __restrict__ Bhi = g_bhi + bOff;
    const __nv_bfloat16* __restrict__ Blo = g_blo + bOff;

    const int nkt = Kpad >> 5;

    // ---- stage loader: 2048 x 16B chunks, 8 per thread ----
    auto load_stage = [&](int kt, int buf) {
        const uint32_t s = sb + buf * STAGE_BYTES;
        const int k0 = kt << 5;
#pragma unroll
        for (int half = 0; half < 2; half++) {
            int cid = half * 256 + tid;
            int row = cid >> 2, ch = cid & 3;
            size_t ga = (size_t)(bm + row) * Kpad + k0 + ch * 8;
            cp16(swz(s + A_HI_OFF, row, ch), Ahi + ga, true);
            cp16(swz(s + A_LO_OFF, row, ch), Alo + ga, true);
            int n = bn + row;
            bool v = n < NV;
            size_t gb = v ? ((size_t)n * Kpad + k0 + ch * 8) : 0;
            cp16(swz(s + B_HI_OFF, row, ch), Bhi + gb, v);
            cp16(swz(s + B_LO_OFF, row, ch), Blo + gb, v);
        }
    };

    float acc[4][4][4];
#pragma unroll
    for (int i = 0; i < 4; i++)
#pragma unroll
        for (int j = 0; j < 4; j++)
#pragma unroll
            for (int q = 0; q < 4; q++) acc[i][j][q] = 0.0f;

    // prologue
    load_stage(0, 0); CP_COMMIT();
    if (nkt > 1) load_stage(1, 1);
    CP_COMMIT();

    const int mid = lane >> 3, r8 = lane & 7;

    for (int kt = 0; kt < nkt; kt++) {
        CP_WAIT1();
        __syncthreads();
        if (kt + 2 < nkt) load_stage(kt + 2, (kt + 2) % 3);
        CP_COMMIT();

        const uint32_t s = sb + (kt % 3) * STAGE_BYTES;
#pragma unroll
        for (int ks = 0; ks < 2; ks++) {
            uint32_t ah[4][4], al[4][4], bh[2][4], bl[2][4];
            // A frags: row = wm*64 + mi*16 + (mid&1)*8 + r8 ; chunk = ks*2 + (mid>>1)
            int arow = wm * 64 + (mid & 1) * 8 + r8;
            int ach = ks * 2 + (mid >> 1);
#pragma unroll
            for (int mi = 0; mi < 4; mi++) {
                LDSM4(ah[mi][0], ah[mi][1], ah[mi][2], ah[mi][3], swz(s + A_HI_OFF, arow + mi * 16, ach));
                LDSM4(al[mi][0], al[mi][1], al[mi][2], al[mi][3], swz(s + A_LO_OFF, arow + mi * 16, ach));
            }
            // B frags: row(n) = wn*32 + nj*16 + (mid>>1)*8 + r8 ; chunk = ks*2 + (mid&1)
            int brow = wn * 32 + (mid >> 1) * 8 + r8;
            int bch = ks * 2 + (mid & 1);
#pragma unroll
            for (int nj = 0; nj < 2; nj++) {
                LDSM4(bh[nj][0], bh[nj][1], bh[nj][2], bh[nj][3], swz(s + B_HI_OFF, brow + nj * 16, bch));
                LDSM4(bl[nj][0], bl[nj][1], bl[nj][2], bl[nj][3], swz(s + B_LO_OFF, brow + nj * 16, bch));
            }
#pragma unroll
            for (int mi = 0; mi < 4; mi++) {
#pragma unroll
                for (int ni = 0; ni < 4; ni++) {
                    uint32_t* bph = &bh[ni >> 1][(ni & 1) * 2];
                    uint32_t* bpl = &bl[ni >> 1][(ni & 1) * 2];
                    MMA(acc[mi][ni], ah[mi], bph[0], bph[1]);
                    MMA(acc[mi][ni], ah[mi], bpl[0], bpl[1]);
                    MMA(acc[mi][ni], al[mi], bph[0], bph[1]);
                }
            }
        }
        __syncthreads();
    }

    // ---- epilogue: scale by wsel, store ----
    const int tg = lane >> 2, tq = lane & 3;
    const int Cm1 = (1 << cShift) - 1;
#pragma unroll
    for (int mi = 0; mi < 4; mi++) {
#pragma unroll
        for (int h = 0; h < 2; h++) {
            int m = bm + wm * 64 + mi * 16 + h * 8 + tg;
            int bI = m >> cShift;
            int c = m & Cm1;
            float* orow = out + ((size_t)bI * C_TOTAL + cOff + c) * NV;
            const float* wrow = g_wsel + (size_t)(cOff + c) * NV;
#pragma unroll
            for (int ni = 0; ni < 4; ni++) {
                int col = bn + wn * 32 + ni * 8 + tq * 2;
                if (col < NV) {
                    float2 wv = *(const float2*)(wrow + col);
                    float2 o;
                    o.x = acc[mi][ni][h * 2 + 0] * wv.x;
                    o.y = acc[mi][ni][h * 2 + 1] * wv.y;
                    *(float2*)(orow + col) = o;
                }
            }
        }
    }
}

// ---------------- launch ----------------
extern "C" void kernel_launch(void* const* d_in, const int* in_sizes, int n_in,
                              void* d_out, int out_size) {
    static const int fsz[4] = {1605632, 802816, 401408, 200704};
    static const int rsz[4] = {62720000, 15680000, 3920000, 980000};
    static const int wsz[4] = {1280000, 2560000, 5120000, 10240000};

    const float* fmap[4] = {0, 0, 0, 0};
    const float* rfp[4]  = {0, 0, 0, 0};
    const float* wptr[4] = {0, 0, 0, 0};
    const void*  roi = 0;

    for (int i = 0; i < n_in; i++) {
        int s = in_sizes[i];
        if (s == NV) { roi = d_in[i]; continue; }
        for (int l = 0; l < 4; l++) {
            if (s == fsz[l]) fmap[l] = (const float*)d_in[i];
            else if (s == rsz[l]) rfp[l]  = (const float*)d_in[i];
            else if (s == wsz[l]) wptr[l] = (const float*)d_in[i];
        }
    }

    static const int    Ks[4]  = {3136, 784, 196, 49};
    static const int    Kp[4]  = {3136, 800, 224, 64};
    static const size_t aOf[4] = {0, 1605632, 2424832, 2883584};
    static const size_t bOf[4] = {0, 25088000, 31488000, 33280000};
    static const int    Cs[4]  = {64, 128, 256, 512};
    static const int    Csh[4] = {6, 7, 8, 9};
    static const int    Co[4]  = {0, 64, 192, 448};

    float* out = (float*)d_out;

    cudaFuncSetAttribute(gemm_mma, cudaFuncAttributeMaxDynamicSharedMemorySize, SMEM_TOTAL);

    auto prep = [&](int l) {
        int M = 8 * Cs[l];
        int n = M * Kp[l];
        split_fmap_kernel<<<(n + 255) / 256, 256>>>(fmap[l], M, Ks[l], Kp[l], aOf[l]);
        gather_tr_kernel<<<dim3(Kp[l] / 32, 32), 256>>>(rfp[l], Ks[l], Kp[l], bOf[l]);
        long long tw = (long long)Cs[l] * NV;
        gather_w_kernel<<<(unsigned)((tw + 255) / 256), 256>>>(wptr[l], Cs[l], Co[l]);
    };
    auto gemm = [&](int l) {
        int M = 8 * Cs[l];
        dim3 grid(M / 128, (NV + 127) / 128);   // m fastest -> B n-tile L2 reuse
        gemm_mma<<<grid, 256, SMEM_TOTAL>>>(aOf[l], bOf[l], Kp[l], Csh[l], Co[l], out);
    };

    // Launch order arranged so ncu (-s 5 -c 1) captures gemm(0) as launch #6:
    // roi(1), split0(2), tr0(3), w0(4), split1(5), gemm0(6), ...
    roi_norm_kernel<<<(NV + 255) / 256, 256>>>((const int*)roi);
    {
        int l = 0;
        int M = 8 * Cs[l];
        int n = M * Kp[l];
        split_fmap_kernel<<<(n + 255) / 256, 256>>>(fmap[l], M, Ks[l], Kp[l], aOf[l]);
        gather_tr_kernel<<<dim3(Kp[l] / 32, 32), 256>>>(rfp[l], Ks[l], Kp[l], bOf[l]);
        long long tw = (long long)Cs[l] * NV;
        gather_w_kernel<<<(unsigned)((tw + 255) / 256), 256>>>(wptr[l], Cs[l], Co[l]);
    }
    {
        int l = 1;
        int M = 8 * Cs[l];
        int n = M * Kp[l];
        split_fmap_kernel<<<(n + 255) / 256, 256>>>(fmap[l], M, Ks[l], Kp[l], aOf[l]);  // launch 5
    }
    gemm(0);                                                                             // launch 6
    {
        int l = 1;
        gather_tr_kernel<<<dim3(Kp[l] / 32, 32), 256>>>(rfp[l], Ks[l], Kp[l], bOf[l]);
        long long tw = (long long)Cs[l] * NV;
        gather_w_kernel<<<(unsigned)((tw + 255) / 256), 256>>>(wptr[l], Cs[l], Co[l]);
    }
    gemm(1);
    prep(2);
    gemm(2);
    prep(3);
    gemm(3);
}

// round 6
// speedup vs baseline: 2.5391x; 1.2051x over previous
#include <cuda_runtime.h>
#include <cuda_fp16.h>
#include <cstdint>

#define NV 8000
#define NVT 20000
#define C_TOTAL 960

// Layer geometry (Kpad = K rounded up to 32)
//   l:      0      1      2      3
//   C:     64    128    256    512     (M = 8*C)
//   K:   3136    784    196     49
//   Kp:  3136    800    224     64
#define KPAD_SUM 4224
#define A_ELEMS 3145728   // sum M*Kpad

// ---------------- scratch (__device__ globals; allocation-free rule) ----------------
__device__ __align__(16) __half g_ahi[A_ELEMS];                      // fp16 hi of fmap
__device__ __align__(16) __half g_bhi[(size_t)NV * KPAD_SUM];        // [8000, Kp] K-major
__device__ __align__(16) __half g_blo[(size_t)NV * KPAD_SUM];        // fp16 residual
__device__ __align__(16) float g_wsel[(size_t)C_TOTAL * NV];

// ---------------- inline roi (int64-vs-int32 dtype detect; values < 20000) ----------
__device__ __forceinline__ bool roi_is64(const int* __restrict__ r32) {
    int acc = 0;
#pragma unroll
    for (int i = 1; i < 32; i += 2) acc |= r32[i];
    return acc == 0;
}

// ---------------- prep kernels ----------------
// fmap [M,K] fp32 -> g_ahi [M,Kpad] fp16 hi, zero-padded
__global__ void split_fmap_kernel(const float* __restrict__ f, int M, int K, int Kpad,
                                  size_t aOff) {
    int idx = blockIdx.x * blockDim.x + threadIdx.x;
    if (idx >= M * Kpad) return;
    int m = idx / Kpad, k = idx - m * Kpad;
    float x = (k < K) ? f[(size_t)m * K + k] : 0.0f;
    g_ahi[aOff + idx] = __float2half_rn(x);
}

// rf [K, 20000] -> g_bhi/g_blo [8000, Kpad] (gather + leaky_relu + transpose + fp16 split)
__global__ void gather_tr_kernel(const float* __restrict__ rf, const int* __restrict__ roi,
                                 int K, int Kpad, size_t bOff) {
    __shared__ float tile[32][257];
    const int tid = threadIdx.x;
    const int p0 = blockIdx.x * 32;
    const int v0 = blockIdx.y * 256;
    const bool is64 = roi_is64(roi);

    int vr = v0 + tid;
    int ri = (vr < NV) ? (is64 ? roi[2 * vr] : roi[vr]) : 0;
#pragma unroll 4
    for (int i = 0; i < 32; i++) {
        int p = p0 + i;
        float x = 0.0f;
        if (p < K && vr < NV) {
            x = rf[(size_t)p * NVT + ri];
            x = (x > 0.0f) ? x : 0.01f * x;
        }
        tile[i][tid] = x;
    }
    __syncthreads();

    const int pl = tid & 31;
    const int vb = tid >> 5;
#pragma unroll 4
    for (int i = 0; i < 32; i++) {
        int vloc = vb + (i << 3);
        int v = v0 + vloc;
        if (v < NV) {
            float x = tile[pl][vloc];
            __half hi = __float2half_rn(x);
            __half lo = __float2half_rn(x - __half2float(hi));
            size_t o = bOff + (size_t)v * Kpad + p0 + pl;
            g_bhi[o] = hi;
            g_blo[o] = lo;
        }
    }
}

__global__ void gather_w_kernel(const float* __restrict__ w, const int* __restrict__ roi,
                                int Cn, int cOff) {
    const bool is64 = roi_is64(roi);
    long long idx = (long long)blockIdx.x * blockDim.x + threadIdx.x;
    if (idx >= (long long)Cn * NV) return;
    int v = (int)(idx % NV);
    int c = (int)(idx / NV);
    int ri = is64 ? roi[2 * v] : roi[v];
    g_wsel[(size_t)(cOff + c) * NV + v] = w[(size_t)c * NVT + (size_t)ri];
}

// ---------------- mma.sync GEMM (fp16 2-pass split) ----------------
// out[b, cOff+c, v] = (Ahi @ (Bhi+Blo)^T)[m, v] * wsel
// BM=128, BN=128, BK=32; 8 warps, each 64(m) x 32(n); 3-stage cp.async pipeline.

#define STAGE_BYTES 24576
#define A_HI_OFF 0
#define B_HI_OFF 8192
#define B_LO_OFF 16384
#define SMEM_TOTAL (3 * STAGE_BYTES)

__device__ __forceinline__ uint32_t smem_u32(const void* p) {
    uint32_t a;
    asm("{ .reg .u64 t; cvta.to.shared.u64 t, %1; cvt.u32.u64 %0, t; }" : "=r"(a) : "l"(p));
    return a;
}
// 64B rows (32 halves); chunk = 16B unit. Swizzle keeps ldmatrix conflict-free.
__device__ __forceinline__ uint32_t swz(uint32_t base, int row, int chunk) {
    return base + (uint32_t)(row * 64 + (chunk ^ ((row >> 1) & 3)) * 16);
}
__device__ __forceinline__ void cp16(uint32_t dst, const void* src, bool v) {
    asm volatile("cp.async.cg.shared.global [%0], [%1], 16, %2;"
                 :: "r"(dst), "l"(src), "r"(v ? 16 : 0));
}
#define CP_COMMIT() asm volatile("cp.async.commit_group;" ::: "memory")
#define CP_WAIT1()  asm volatile("cp.async.wait_group 1;" ::: "memory")

#define LDSM4(r0, r1, r2, r3, a) \
    asm volatile("ldmatrix.sync.aligned.m8n8.x4.shared.b16 {%0,%1,%2,%3}, [%4];" \
                 : "=r"(r0), "=r"(r1), "=r"(r2), "=r"(r3) : "r"(a))

#define MMA(d, a, b0_, b1_) \
    asm volatile("mma.sync.aligned.m16n8k16.row.col.f32.f16.f16.f32 " \
                 "{%0,%1,%2,%3}, {%4,%5,%6,%7}, {%8,%9}, {%0,%1,%2,%3};" \
                 : "+f"((d)[0]), "+f"((d)[1]), "+f"((d)[2]), "+f"((d)[3]) \
                 : "r"((a)[0]), "r"((a)[1]), "r"((a)[2]), "r"((a)[3]), "r"(b0_), "r"(b1_))

__global__ void __launch_bounds__(256, 2)
gemm_mma(size_t aOff, size_t bOff, int Kpad, int cShift, int cOff, float* __restrict__ out)
{
    extern __shared__ char smem[];
    const uint32_t sb = smem_u32(smem);
    const int tid = threadIdx.x;
    const int lane = tid & 31;
    const int w = tid >> 5;
    const int wm = w >> 2;          // 0..1
    const int wn = w & 3;           // 0..3
    const int bm = blockIdx.x * 128;
    const int bn = blockIdx.y * 128;

    const __half* __restrict__ Ahi = g_ahi + aOff;
    const __half* __restrict__ Bhi = g_bhi + bOff;
    const __half* __restrict__ Blo = g_blo + bOff;

    const int nkt = Kpad >> 5;

    // ---- stage loader: 1536 x 16B chunks, 6 per thread ----
    auto load_stage = [&](int kt, int buf) {
        const uint32_t s = sb + buf * STAGE_BYTES;
        const int k0 = kt << 5;
#pragma unroll
        for (int half_ = 0; half_ < 2; half_++) {
            int cid = half_ * 256 + tid;
            int row = cid >> 2, ch = cid & 3;
            size_t ga = (size_t)(bm + row) * Kpad + k0 + ch * 8;
            cp16(swz(s + A_HI_OFF, row, ch), Ahi + ga, true);
            int n = bn + row;
            bool v = n < NV;
            size_t gb = v ? ((size_t)n * Kpad + k0 + ch * 8) : 0;
            cp16(swz(s + B_HI_OFF, row, ch), Bhi + gb, v);
            cp16(swz(s + B_LO_OFF, row, ch), Blo + gb, v);
        }
    };

    float acc[4][4][4];
#pragma unroll
    for (int i = 0; i < 4; i++)
#pragma unroll
        for (int j = 0; j < 4; j++)
#pragma unroll
            for (int q = 0; q < 4; q++) acc[i][j][q] = 0.0f;

    // prologue
    load_stage(0, 0); CP_COMMIT();
    if (nkt > 1) load_stage(1, 1);
    CP_COMMIT();

    const int mid = lane >> 3, r8 = lane & 7;

    for (int kt = 0; kt < nkt; kt++) {
        CP_WAIT1();
        __syncthreads();
        if (kt + 2 < nkt) load_stage(kt + 2, (kt + 2) % 3);
        CP_COMMIT();

        const uint32_t s = sb + (kt % 3) * STAGE_BYTES;
#pragma unroll
        for (int ks = 0; ks < 2; ks++) {
            uint32_t ah[4][4], bh[2][4], bl[2][4];
            // A frags: row = wm*64 + mi*16 + (mid&1)*8 + r8 ; chunk = ks*2 + (mid>>1)
            int arow = wm * 64 + (mid & 1) * 8 + r8;
            int ach = ks * 2 + (mid >> 1);
#pragma unroll
            for (int mi = 0; mi < 4; mi++)
                LDSM4(ah[mi][0], ah[mi][1], ah[mi][2], ah[mi][3], swz(s + A_HI_OFF, arow + mi * 16, ach));
            // B frags: row(n) = wn*32 + nj*16 + (mid>>1)*8 + r8 ; chunk = ks*2 + (mid&1)
            int brow = wn * 32 + (mid >> 1) * 8 + r8;
            int bch = ks * 2 + (mid & 1);
#pragma unroll
            for (int nj = 0; nj < 2; nj++) {
                LDSM4(bh[nj][0], bh[nj][1], bh[nj][2], bh[nj][3], swz(s + B_HI_OFF, brow + nj * 16, bch));
                LDSM4(bl[nj][0], bl[nj][1], bl[nj][2], bl[nj][3], swz(s + B_LO_OFF, brow + nj * 16, bch));
            }
#pragma unroll
            for (int mi = 0; mi < 4; mi++) {
#pragma unroll
                for (int ni = 0; ni < 4; ni++) {
                    uint32_t* bph = &bh[ni >> 1][(ni & 1) * 2];
                    uint32_t* bpl = &bl[ni >> 1][(ni & 1) * 2];
                    MMA(acc[mi][ni], ah[mi], bph[0], bph[1]);
                    MMA(acc[mi][ni], ah[mi], bpl[0], bpl[1]);
                }
            }
        }
        __syncthreads();
    }

    // ---- epilogue: scale by wsel, store ----
    const int tg = lane >> 2, tq = lane & 3;
    const int Cm1 = (1 << cShift) - 1;
#pragma unroll
    for (int mi = 0; mi < 4; mi++) {
#pragma unroll
        for (int h = 0; h < 2; h++) {
            int m = bm + wm * 64 + mi * 16 + h * 8 + tg;
            int bI = m >> cShift;
            int c = m & Cm1;
            float* orow = out + ((size_t)bI * C_TOTAL + cOff + c) * NV;
            const float* wrow = g_wsel + (size_t)(cOff + c) * NV;
#pragma unroll
            for (int ni = 0; ni < 4; ni++) {
                int col = bn + wn * 32 + ni * 8 + tq * 2;
                if (col < NV) {
                    float2 wv = *(const float2*)(wrow + col);
                    float2 o;
                    o.x = acc[mi][ni][h * 2 + 0] * wv.x;
                    o.y = acc[mi][ni][h * 2 + 1] * wv.y;
                    *(float2*)(orow + col) = o;
                }
            }
        }
    }
}

// ---------------- launch ----------------
extern "C" void kernel_launch(void* const* d_in, const int* in_sizes, int n_in,
                              void* d_out, int out_size) {
    static const int fsz[4] = {1605632, 802816, 401408, 200704};
    static const int rsz[4] = {62720000, 15680000, 3920000, 980000};
    static const int wsz[4] = {1280000, 2560000, 5120000, 10240000};

    const float* fmap[4] = {0, 0, 0, 0};
    const float* rfp[4]  = {0, 0, 0, 0};
    const float* wptr[4] = {0, 0, 0, 0};
    const int*   roi = 0;

    for (int i = 0; i < n_in; i++) {
        int s = in_sizes[i];
        if (s == NV) { roi = (const int*)d_in[i]; continue; }
        for (int l = 0; l < 4; l++) {
            if (s == fsz[l]) fmap[l] = (const float*)d_in[i];
            else if (s == rsz[l]) rfp[l]  = (const float*)d_in[i];
            else if (s == wsz[l]) wptr[l] = (const float*)d_in[i];
        }
    }

    static const int    Ks[4]  = {3136, 784, 196, 49};
    static const int    Kp[4]  = {3136, 800, 224, 64};
    static const size_t aOf[4] = {0, 1605632, 2424832, 2883584};
    static const size_t bOf[4] = {0, 25088000, 31488000, 33280000};
    static const int    Cs[4]  = {64, 128, 256, 512};
    static const int    Csh[4] = {6, 7, 8, 9};
    static const int    Co[4]  = {0, 64, 192, 448};

    float* out = (float*)d_out;

    cudaFuncSetAttribute(gemm_mma, cudaFuncAttributeMaxDynamicSharedMemorySize, SMEM_TOTAL);

    auto prep = [&](int l) {
        int M = 8 * Cs[l];
        int n = M * Kp[l];
        split_fmap_kernel<<<(n + 255) / 256, 256>>>(fmap[l], M, Ks[l], Kp[l], aOf[l]);
        gather_tr_kernel<<<dim3(Kp[l] / 32, 32), 256>>>(rfp[l], roi, Ks[l], Kp[l], bOf[l]);
        long long tw = (long long)Cs[l] * NV;
        gather_w_kernel<<<(unsigned)((tw + 255) / 256), 256>>>(wptr[l], roi, Cs[l], Co[l]);
    };
    auto gemm = [&](int l) {
        int M = 8 * Cs[l];
        dim3 grid(M / 128, (NV + 127) / 128);   // m fastest -> B n-tile L2 reuse
        gemm_mma<<<grid, 256, SMEM_TOTAL>>>(aOf[l], bOf[l], Kp[l], Csh[l], Co[l], out);
    };

    // Launch order: ncu empirically captures launch #4 -> make that gemm(0).
    prep(0);      // launches 1-3 (split0, tr0, w0)
    gemm(0);      // launch 4  <- profiled
    prep(1);
    gemm(1);
    prep(2);
    gemm(2);
    prep(3);
    gemm(3);
}

// round 7
// speedup vs baseline: 3.1324x; 1.2337x over previous
#include <cuda_runtime.h>
#include <cuda_fp16.h>
#include <cstdint>

#define NV 8000
#define NVT 20000
#define C_TOTAL 960
#define KPAD_SUM 4224
#define A_ELEMS 3145728   // sum M*Kpad

// ---------------- scratch (__device__ globals; allocation-free rule) ----------------
__device__ __align__(16) __half g_ahi[A_ELEMS];                  // fp16 hi of fmap
__device__ __align__(16) __half g_alo[A_ELEMS];                  // fp16 residual of fmap
__device__ __align__(16) __half g_bhi[(size_t)NV * KPAD_SUM];    // [8000, Kp] K-major fp16
__device__ __align__(16) float g_wsel[(size_t)C_TOTAL * NV];

// ---------------- roi dtype detect (int64 vs int32; values < 20000) ----------------
__device__ __forceinline__ bool roi_is64(const int* __restrict__ r32) {
    int acc = 0;
#pragma unroll
    for (int i = 1; i < 32; i += 2) acc |= r32[i];
    return acc == 0;
}

// ---------------- merged prep kernels ----------------
// fmap fp32 -> g_ahi/g_alo (hi + residual), zero-padded; all 4 layers, flat index
__global__ void split_all(const float* __restrict__ f0, const float* __restrict__ f1,
                          const float* __restrict__ f2, const float* __restrict__ f3) {
    int idx = blockIdx.x * 256 + threadIdx.x;
    const float* f; int K, Kpad, base;
    if (idx < 1605632)      { f = f0; K = 3136; Kpad = 3136; base = 0; }
    else if (idx < 2424832) { f = f1; K = 784;  Kpad = 800;  base = 1605632; }
    else if (idx < 2883584) { f = f2; K = 196;  Kpad = 224;  base = 2424832; }
    else if (idx < A_ELEMS) { f = f3; K = 49;   Kpad = 64;   base = 2883584; }
    else return;
    int local = idx - base;
    int m = local / Kpad, k = local - m * Kpad;
    float x = (k < K) ? f[(size_t)m * K + k] : 0.0f;
    __half hi = __float2half_rn(x);
    g_ahi[idx] = hi;
    g_alo[idx] = __float2half_rn(x - __half2float(hi));
}

// rf -> g_bhi (gather + leaky_relu + transpose + fp16); all 4 layers.
// grid.x = 132 p-blocks (98 + 25 + 7 + 2), grid.y = 32 v-blocks of 256.
__global__ void gather_tr_all(const float* __restrict__ r0, const float* __restrict__ r1,
                              const float* __restrict__ r2, const float* __restrict__ r3,
                              const int* __restrict__ roi) {
    __shared__ float tile[32][257];
    const int pb = blockIdx.x;
    const float* rf; int K, Kpad, pbase; size_t bOff;
    if (pb < 98)       { rf = r0; K = 3136; Kpad = 3136; bOff = 0;        pbase = 0; }
    else if (pb < 123) { rf = r1; K = 784;  Kpad = 800;  bOff = 25088000; pbase = 98; }
    else if (pb < 130) { rf = r2; K = 196;  Kpad = 224;  bOff = 31488000; pbase = 123; }
    else               { rf = r3; K = 49;   Kpad = 64;   bOff = 33280000; pbase = 130; }
    const int p0 = (pb - pbase) * 32;
    const int v0 = blockIdx.y * 256;
    const int tid = threadIdx.x;
    const bool is64 = roi_is64(roi);

    int vr = v0 + tid;
    int ri = (vr < NV) ? (is64 ? roi[2 * vr] : roi[vr]) : 0;
#pragma unroll 4
    for (int i = 0; i < 32; i++) {
        int p = p0 + i;
        float x = 0.0f;
        if (p < K && vr < NV) {
            x = rf[(size_t)p * NVT + ri];
            x = (x > 0.0f) ? x : 0.01f * x;
        }
        tile[i][tid] = x;
    }
    __syncthreads();

    const int pl = tid & 31;
    const int vb = tid >> 5;
#pragma unroll 4
    for (int i = 0; i < 32; i++) {
        int vloc = vb + (i << 3);
        int v = v0 + vloc;
        if (v < NV)
            g_bhi[bOff + (size_t)v * Kpad + p0 + pl] = __float2half_rn(tile[pl][vloc]);
    }
}

// w gather; all layers, flat over 960 x 8000 rows
__global__ void gather_w_all(const float* __restrict__ w0, const float* __restrict__ w1,
                             const float* __restrict__ w2, const float* __restrict__ w3,
                             const int* __restrict__ roi) {
    const bool is64 = roi_is64(roi);
    long long idx = (long long)blockIdx.x * 256 + threadIdx.x;
    if (idx >= (long long)C_TOTAL * NV) return;
    int v = (int)(idx % NV);
    int c = (int)(idx / NV);
    const float* w; int lc;
    if (c < 64)       { w = w0; lc = c; }
    else if (c < 192) { w = w1; lc = c - 64; }
    else if (c < 448) { w = w2; lc = c - 192; }
    else              { w = w3; lc = c - 448; }
    int ri = is64 ? roi[2 * v] : roi[v];
    g_wsel[(size_t)c * NV + v] = w[(size_t)lc * NVT + (size_t)ri];
}

// ---------------- fused mma.sync GEMM over all layers ----------------
// out[b, c, v] = ((Ahi+Alo) @ Bhi^T)[m, v] * wsel
// BM=128, BN=128, BK=32; 8 warps as 4(m) x 2(n), warp tile 32x64;
// 4-stage cp.async pipeline, ONE __syncthreads per k-iteration.

#define STAGE_BYTES 24576
#define A_HI_OFF 0
#define A_LO_OFF 8192
#define B_HI_OFF 16384
#define SMEM_TOTAL (4 * STAGE_BYTES)   // 96 KB

__device__ __forceinline__ uint32_t smem_u32(const void* p) {
    uint32_t a;
    asm("{ .reg .u64 t; cvta.to.shared.u64 t, %1; cvt.u32.u64 %0, t; }" : "=r"(a) : "l"(p));
    return a;
}
// 64B rows (32 halves); chunk = 16B unit; conflict-free for ldmatrix
__device__ __forceinline__ uint32_t swz(uint32_t base, int row, int chunk) {
    return base + (uint32_t)(row * 64 + (chunk ^ ((row >> 1) & 3)) * 16);
}
__device__ __forceinline__ void cp16(uint32_t dst, const void* src, bool v) {
    asm volatile("cp.async.cg.shared.global [%0], [%1], 16, %2;"
                 :: "r"(dst), "l"(src), "r"(v ? 16 : 0));
}
#define CP_COMMIT() asm volatile("cp.async.commit_group;" ::: "memory")
#define CP_WAIT2()  asm volatile("cp.async.wait_group 2;" ::: "memory")

#define LDSM4(r0, r1, r2, r3, a) \
    asm volatile("ldmatrix.sync.aligned.m8n8.x4.shared.b16 {%0,%1,%2,%3}, [%4];" \
                 : "=r"(r0), "=r"(r1), "=r"(r2), "=r"(r3) : "r"(a))

#define MMA(d, a, b0_, b1_) \
    asm volatile("mma.sync.aligned.m16n8k16.row.col.f32.f16.f16.f32 " \
                 "{%0,%1,%2,%3}, {%4,%5,%6,%7}, {%8,%9}, {%0,%1,%2,%3};" \
                 : "+f"((d)[0]), "+f"((d)[1]), "+f"((d)[2]), "+f"((d)[3]) \
                 : "r"((a)[0]), "r"((a)[1]), "r"((a)[2]), "r"((a)[3]), "r"(b0_), "r"(b1_))

__global__ void __launch_bounds__(256, 2)
gemm_all(float* __restrict__ out)
{
    extern __shared__ char smem[];
    const uint32_t sb = smem_u32(smem);
    const int tid = threadIdx.x;
    const int lane = tid & 31;
    const int w = tid >> 5;
    const int wm = w >> 1;          // 0..3 (m)
    const int wn = w & 1;           // 0..1 (n)

    // tile decode: layer-0 tiles first (longest-job-first)
    const int t = blockIdx.x;
    int Kpad, cShift, cOff, mtiles, base; size_t aOff, bOff;
    if (t < 252)       { base = 0;    mtiles = 4;  Kpad = 3136; aOff = 0;       bOff = 0;        cShift = 6; cOff = 0; }
    else if (t < 756)  { base = 252;  mtiles = 8;  Kpad = 800;  aOff = 1605632; bOff = 25088000; cShift = 7; cOff = 64; }
    else if (t < 1764) { base = 756;  mtiles = 16; Kpad = 224;  aOff = 2424832; bOff = 31488000; cShift = 8; cOff = 192; }
    else               { base = 1764; mtiles = 32; Kpad = 64;   aOff = 2883584; bOff = 33280000; cShift = 9; cOff = 448; }
    const int local = t - base;
    const int bm = (local % mtiles) * 128;   // m fastest -> B v-tile L2 reuse
    const int bn = (local / mtiles) * 128;

    const __half* __restrict__ Ahi = g_ahi + aOff;
    const __half* __restrict__ Alo = g_alo + aOff;
    const __half* __restrict__ Bhi = g_bhi + bOff;

    const int nkt = Kpad >> 5;

    // ---- stage loader: 512 chunk-ids x 3 arrays ----
    auto load_stage = [&](int kt, int buf) {
        const uint32_t s = sb + buf * STAGE_BYTES;
        const int k0 = kt << 5;
#pragma unroll
        for (int hh = 0; hh < 2; hh++) {
            int cid = hh * 256 + tid;
            int row = cid >> 2, ch = cid & 3;
            size_t ga = (size_t)(bm + row) * Kpad + k0 + ch * 8;
            cp16(swz(s + A_HI_OFF, row, ch), Ahi + ga, true);
            cp16(swz(s + A_LO_OFF, row, ch), Alo + ga, true);
            int n = bn + row;
            bool v = n < NV;
            size_t gb = v ? ((size_t)n * Kpad + k0 + ch * 8) : 0;
            cp16(swz(s + B_HI_OFF, row, ch), Bhi + gb, v);
        }
    };

    float acc[2][8][4];
#pragma unroll
    for (int i = 0; i < 2; i++)
#pragma unroll
        for (int j = 0; j < 8; j++)
#pragma unroll
            for (int q = 0; q < 4; q++) acc[i][j][q] = 0.0f;

    // prologue: fill 3 stages (nkt >= 2 always; guard stage 2)
    load_stage(0, 0); CP_COMMIT();
    if (nkt > 1) load_stage(1, 1);
    CP_COMMIT();
    if (nkt > 2) load_stage(2, 2);
    CP_COMMIT();

    const int mid = lane >> 3, r8 = lane & 7;

    for (int kt = 0; kt < nkt; kt++) {
        CP_WAIT2();          // stage kt complete
        __syncthreads();     // safe: all warps past compute kt-1 -> stage (kt+3)&3 free
        if (kt + 3 < nkt) load_stage(kt + 3, (kt + 3) & 3);
        CP_COMMIT();

        const uint32_t s = sb + (kt & 3) * STAGE_BYTES;
#pragma unroll
        for (int ks = 0; ks < 2; ks++) {
            uint32_t ah[2][4], al[2][4], bh[4][4];
            int arow = wm * 32 + (mid & 1) * 8 + r8;
            int ach = ks * 2 + (mid >> 1);
#pragma unroll
            for (int mi = 0; mi < 2; mi++) {
                LDSM4(ah[mi][0], ah[mi][1], ah[mi][2], ah[mi][3], swz(s + A_HI_OFF, arow + mi * 16, ach));
                LDSM4(al[mi][0], al[mi][1], al[mi][2], al[mi][3], swz(s + A_LO_OFF, arow + mi * 16, ach));
            }
            int brow = wn * 64 + (mid >> 1) * 8 + r8;
            int bch = ks * 2 + (mid & 1);
#pragma unroll
            for (int nj = 0; nj < 4; nj++)
                LDSM4(bh[nj][0], bh[nj][1], bh[nj][2], bh[nj][3], swz(s + B_HI_OFF, brow + nj * 16, bch));
#pragma unroll
            for (int mi = 0; mi < 2; mi++) {
#pragma unroll
                for (int ni = 0; ni < 8; ni++) {
                    uint32_t* bp = &bh[ni >> 1][(ni & 1) * 2];
                    MMA(acc[mi][ni], ah[mi], bp[0], bp[1]);
                    MMA(acc[mi][ni], al[mi], bp[0], bp[1]);
                }
            }
        }
    }

    // ---- epilogue: scale by wsel, store ----
    const int tg = lane >> 2, tq = lane & 3;
    const int Cm1 = (1 << cShift) - 1;
#pragma unroll
    for (int mi = 0; mi < 2; mi++) {
#pragma unroll
        for (int h = 0; h < 2; h++) {
            int m = bm + wm * 32 + mi * 16 + h * 8 + tg;
            int bI = m >> cShift;
            int c = m & Cm1;
            float* orow = out + ((size_t)bI * C_TOTAL + cOff + c) * NV;
            const float* wrow = g_wsel + (size_t)(cOff + c) * NV;
#pragma unroll
            for (int ni = 0; ni < 8; ni++) {
                int col = bn + wn * 64 + ni * 8 + tq * 2;
                if (col < NV) {
                    float2 wv = *(const float2*)(wrow + col);
                    float2 o;
                    o.x = acc[mi][ni][h * 2 + 0] * wv.x;
                    o.y = acc[mi][ni][h * 2 + 1] * wv.y;
                    *(float2*)(orow + col) = o;
                }
            }
        }
    }
}

// ---------------- launch ----------------
extern "C" void kernel_launch(void* const* d_in, const int* in_sizes, int n_in,
                              void* d_out, int out_size) {
    static const int fsz[4] = {1605632, 802816, 401408, 200704};
    static const int rsz[4] = {62720000, 15680000, 3920000, 980000};
    static const int wsz[4] = {1280000, 2560000, 5120000, 10240000};

    const float* fmap[4] = {0, 0, 0, 0};
    const float* rfp[4]  = {0, 0, 0, 0};
    const float* wptr[4] = {0, 0, 0, 0};
    const int*   roi = 0;

    for (int i = 0; i < n_in; i++) {
        int s = in_sizes[i];
        if (s == NV) { roi = (const int*)d_in[i]; continue; }
        for (int l = 0; l < 4; l++) {
            if (s == fsz[l]) fmap[l] = (const float*)d_in[i];
            else if (s == rsz[l]) rfp[l]  = (const float*)d_in[i];
            else if (s == wsz[l]) wptr[l] = (const float*)d_in[i];
        }
    }

    float* out = (float*)d_out;

    cudaFuncSetAttribute(gemm_all, cudaFuncAttributeMaxDynamicSharedMemorySize, SMEM_TOTAL);

    split_all<<<A_ELEMS / 256, 256>>>(fmap[0], fmap[1], fmap[2], fmap[3]);          // 1
    gather_tr_all<<<dim3(132, 32), 256>>>(rfp[0], rfp[1], rfp[2], rfp[3], roi);     // 2
    gather_w_all<<<(int)(((long long)C_TOTAL * NV + 255) / 256), 256>>>(            // 3
        wptr[0], wptr[1], wptr[2], wptr[3], roi);
    gemm_all<<<3780, 256, SMEM_TOTAL>>>(out);                                        // 4 <- profiled
}

// round 8
// speedup vs baseline: 3.8379x; 1.2252x over previous
#include <cuda_runtime.h>
#include <cuda_fp16.h>
#include <cstdint>

#define NV 8000
#define NVT 20000
#define C_TOTAL 960
#define KPAD_SUM 4224
#define A_ELEMS 3145728   // sum M*Kpad

// ---------------- scratch (__device__ globals; allocation-free rule) ----------------
__device__ __align__(16) __half g_ahi[A_ELEMS];                  // fp16 fmap
__device__ __align__(16) __half g_bhi[(size_t)NV * KPAD_SUM];    // [8000, Kp] K-major fp16
__device__ __align__(16) float g_wsel[(size_t)C_TOTAL * NV];

// ---------------- roi dtype detect (int64 vs int32; values < 20000) ----------------
__device__ __forceinline__ bool roi_is64(const int* __restrict__ r32) {
    int acc = 0;
#pragma unroll
    for (int i = 1; i < 32; i += 2) acc |= r32[i];
    return acc == 0;
}

// ---------------- merged prep kernels ----------------
// fmap fp32 -> g_ahi fp16, zero-padded; all 4 layers, flat index
__global__ void split_all(const float* __restrict__ f0, const float* __restrict__ f1,
                          const float* __restrict__ f2, const float* __restrict__ f3) {
    int idx = blockIdx.x * 256 + threadIdx.x;
    const float* f; int K, Kpad, base;
    if (idx < 1605632)      { f = f0; K = 3136; Kpad = 3136; base = 0; }
    else if (idx < 2424832) { f = f1; K = 784;  Kpad = 800;  base = 1605632; }
    else if (idx < 2883584) { f = f2; K = 196;  Kpad = 224;  base = 2424832; }
    else if (idx < A_ELEMS) { f = f3; K = 49;   Kpad = 64;   base = 2883584; }
    else return;
    int local = idx - base;
    int m = local / Kpad, k = local - m * Kpad;
    float x = (k < K) ? f[(size_t)m * K + k] : 0.0f;
    g_ahi[idx] = __float2half_rn(x);
}

// rf -> g_bhi (gather + leaky_relu + transpose + fp16); all 4 layers.
// grid.x = 132 p-blocks (98 + 25 + 7 + 2), grid.y = 32 v-blocks of 256.
__global__ void gather_tr_all(const float* __restrict__ r0, const float* __restrict__ r1,
                              const float* __restrict__ r2, const float* __restrict__ r3,
                              const int* __restrict__ roi) {
    __shared__ float tile[32][257];
    const int pb = blockIdx.x;
    const float* rf; int K, Kpad, pbase; size_t bOff;
    if (pb < 98)       { rf = r0; K = 3136; Kpad = 3136; bOff = 0;        pbase = 0; }
    else if (pb < 123) { rf = r1; K = 784;  Kpad = 800;  bOff = 25088000; pbase = 98; }
    else if (pb < 130) { rf = r2; K = 196;  Kpad = 224;  bOff = 31488000; pbase = 123; }
    else               { rf = r3; K = 49;   Kpad = 64;   bOff = 33280000; pbase = 130; }
    const int p0 = (pb - pbase) * 32;
    const int v0 = blockIdx.y * 256;
    const int tid = threadIdx.x;
    const bool is64 = roi_is64(roi);

    int vr = v0 + tid;
    int ri = (vr < NV) ? (is64 ? roi[2 * vr] : roi[vr]) : 0;
#pragma unroll 4
    for (int i = 0; i < 32; i++) {
        int p = p0 + i;
        float x = 0.0f;
        if (p < K && vr < NV) {
            x = rf[(size_t)p * NVT + ri];
            x = (x > 0.0f) ? x : 0.01f * x;
        }
        tile[i][tid] = x;
    }
    __syncthreads();

    const int pl = tid & 31;
    const int vb = tid >> 5;
#pragma unroll 4
    for (int i = 0; i < 32; i++) {
        int vloc = vb + (i << 3);
        int v = v0 + vloc;
        if (v < NV)
            g_bhi[bOff + (size_t)v * Kpad + p0 + pl] = __float2half_rn(tile[pl][vloc]);
    }
}

// w gather; all layers, flat over 960 x 8000 rows
__global__ void gather_w_all(const float* __restrict__ w0, const float* __restrict__ w1,
                             const float* __restrict__ w2, const float* __restrict__ w3,
                             const int* __restrict__ roi) {
    const bool is64 = roi_is64(roi);
    long long idx = (long long)blockIdx.x * 256 + threadIdx.x;
    if (idx >= (long long)C_TOTAL * NV) return;
    int v = (int)(idx % NV);
    int c = (int)(idx / NV);
    const float* w; int lc;
    if (c < 64)       { w = w0; lc = c; }
    else if (c < 192) { w = w1; lc = c - 64; }
    else if (c < 448) { w = w2; lc = c - 192; }
    else              { w = w3; lc = c - 448; }
    int ri = is64 ? roi[2 * v] : roi[v];
    g_wsel[(size_t)c * NV + v] = w[(size_t)lc * NVT + (size_t)ri];
}

// ---------------- fused single-pass fp16 mma.sync GEMM over all layers ----------------
// out[b, c, v] = (Ahi @ Bhi^T)[m, v] * wsel
// BM=128, BN=128, BK=32; 8 warps as 4(m) x 2(n), warp tile 32x64;
// 4-stage cp.async pipeline, ONE __syncthreads per k-iteration.

#define STAGE_BYTES 16384
#define A_HI_OFF 0
#define B_HI_OFF 8192
#define SMEM_TOTAL (4 * STAGE_BYTES)   // 64 KB

__device__ __forceinline__ uint32_t smem_u32(const void* p) {
    uint32_t a;
    asm("{ .reg .u64 t; cvta.to.shared.u64 t, %1; cvt.u32.u64 %0, t; }" : "=r"(a) : "l"(p));
    return a;
}
// 64B rows (32 halves); chunk = 16B unit; conflict-free for ldmatrix
__device__ __forceinline__ uint32_t swz(uint32_t base, int row, int chunk) {
    return base + (uint32_t)(row * 64 + (chunk ^ ((row >> 1) & 3)) * 16);
}
__device__ __forceinline__ void cp16(uint32_t dst, const void* src, bool v) {
    asm volatile("cp.async.cg.shared.global [%0], [%1], 16, %2;"
                 :: "r"(dst), "l"(src), "r"(v ? 16 : 0));
}
#define CP_COMMIT() asm volatile("cp.async.commit_group;" ::: "memory")
#define CP_WAIT2()  asm volatile("cp.async.wait_group 2;" ::: "memory")

#define LDSM4(r0, r1, r2, r3, a) \
    asm volatile("ldmatrix.sync.aligned.m8n8.x4.shared.b16 {%0,%1,%2,%3}, [%4];" \
                 : "=r"(r0), "=r"(r1), "=r"(r2), "=r"(r3) : "r"(a))

#define MMA(d, a, b0_, b1_) \
    asm volatile("mma.sync.aligned.m16n8k16.row.col.f32.f16.f16.f32 " \
                 "{%0,%1,%2,%3}, {%4,%5,%6,%7}, {%8,%9}, {%0,%1,%2,%3};" \
                 : "+f"((d)[0]), "+f"((d)[1]), "+f"((d)[2]), "+f"((d)[3]) \
                 : "r"((a)[0]), "r"((a)[1]), "r"((a)[2]), "r"((a)[3]), "r"(b0_), "r"(b1_))

__global__ void __launch_bounds__(256, 2)
gemm_all(float* __restrict__ out)
{
    extern __shared__ char smem[];
    const uint32_t sb = smem_u32(smem);
    const int tid = threadIdx.x;
    const int lane = tid & 31;
    const int w = tid >> 5;
    const int wm = w >> 1;          // 0..3 (m)
    const int wn = w & 1;           // 0..1 (n)

    // tile decode: layer-0 tiles first (longest-job-first)
    const int t = blockIdx.x;
    int Kpad, cShift, cOff, mtiles, base; size_t aOff, bOff;
    if (t < 252)       { base = 0;    mtiles = 4;  Kpad = 3136; aOff = 0;       bOff = 0;        cShift = 6; cOff = 0; }
    else if (t < 756)  { base = 252;  mtiles = 8;  Kpad = 800;  aOff = 1605632; bOff = 25088000; cShift = 7; cOff = 64; }
    else if (t < 1764) { base = 756;  mtiles = 16; Kpad = 224;  aOff = 2424832; bOff = 31488000; cShift = 8; cOff = 192; }
    else               { base = 1764; mtiles = 32; Kpad = 64;   aOff = 2883584; bOff = 33280000; cShift = 9; cOff = 448; }
    const int local = t - base;
    const int bm = (local % mtiles) * 128;   // m fastest -> B v-tile L2 reuse
    const int bn = (local / mtiles) * 128;

    const __half* __restrict__ Ahi = g_ahi + aOff;
    const __half* __restrict__ Bhi = g_bhi + bOff;

    const int nkt = Kpad >> 5;

    // ---- stage loader: 512 chunk-ids x 2 arrays, 4 cp.async per thread ----
    auto load_stage = [&](int kt, int buf) {
        const uint32_t s = sb + buf * STAGE_BYTES;
        const int k0 = kt << 5;
#pragma unroll
        for (int hh = 0; hh < 2; hh++) {
            int cid = hh * 256 + tid;
            int row = cid >> 2, ch = cid & 3;
            size_t ga = (size_t)(bm + row) * Kpad + k0 + ch * 8;
            cp16(swz(s + A_HI_OFF, row, ch), Ahi + ga, true);
            int n = bn + row;
            bool v = n < NV;
            size_t gb = v ? ((size_t)n * Kpad + k0 + ch * 8) : 0;
            cp16(swz(s + B_HI_OFF, row, ch), Bhi + gb, v);
        }
    };

    float acc[2][8][4];
#pragma unroll
    for (int i = 0; i < 2; i++)
#pragma unroll
        for (int j = 0; j < 8; j++)
#pragma unroll
            for (int q = 0; q < 4; q++) acc[i][j][q] = 0.0f;

    // prologue: fill 3 stages
    load_stage(0, 0); CP_COMMIT();
    if (nkt > 1) load_stage(1, 1);
    CP_COMMIT();
    if (nkt > 2) load_stage(2, 2);
    CP_COMMIT();

    const int mid = lane >> 3, r8 = lane & 7;

    for (int kt = 0; kt < nkt; kt++) {
        CP_WAIT2();          // stage kt complete
        __syncthreads();     // all warps past compute kt-1 -> stage (kt+3)&3 free
        if (kt + 3 < nkt) load_stage(kt + 3, (kt + 3) & 3);
        CP_COMMIT();

        const uint32_t s = sb + (kt & 3) * STAGE_BYTES;
#pragma unroll
        for (int ks = 0; ks < 2; ks++) {
            uint32_t ah[2][4], bh[4][4];
            int arow = wm * 32 + (mid & 1) * 8 + r8;
            int ach = ks * 2 + (mid >> 1);
#pragma unroll
            for (int mi = 0; mi < 2; mi++)
                LDSM4(ah[mi][0], ah[mi][1], ah[mi][2], ah[mi][3], swz(s + A_HI_OFF, arow + mi * 16, ach));
            int brow = wn * 64 + (mid >> 1) * 8 + r8;
            int bch = ks * 2 + (mid & 1);
#pragma unroll
            for (int nj = 0; nj < 4; nj++)
                LDSM4(bh[nj][0], bh[nj][1], bh[nj][2], bh[nj][3], swz(s + B_HI_OFF, brow + nj * 16, bch));
#pragma unroll
            for (int mi = 0; mi < 2; mi++) {
#pragma unroll
                for (int ni = 0; ni < 8; ni++) {
                    uint32_t* bp = &bh[ni >> 1][(ni & 1) * 2];
                    MMA(acc[mi][ni], ah[mi], bp[0], bp[1]);
                }
            }
        }
    }

    // ---- epilogue: scale by wsel, store ----
    const int tg = lane >> 2, tq = lane & 3;
    const int Cm1 = (1 << cShift) - 1;
#pragma unroll
    for (int mi = 0; mi < 2; mi++) {
#pragma unroll
        for (int h = 0; h < 2; h++) {
            int m = bm + wm * 32 + mi * 16 + h * 8 + tg;
            int bI = m >> cShift;
            int c = m & Cm1;
            float* orow = out + ((size_t)bI * C_TOTAL + cOff + c) * NV;
            const float* wrow = g_wsel + (size_t)(cOff + c) * NV;
#pragma unroll
            for (int ni = 0; ni < 8; ni++) {
                int col = bn + wn * 64 + ni * 8 + tq * 2;
                if (col < NV) {
                    float2 wv = *(const float2*)(wrow + col);
                    float2 o;
                    o.x = acc[mi][ni][h * 2 + 0] * wv.x;
                    o.y = acc[mi][ni][h * 2 + 1] * wv.y;
                    *(float2*)(orow + col) = o;
                }
            }
        }
    }
}

// ---------------- launch ----------------
extern "C" void kernel_launch(void* const* d_in, const int* in_sizes, int n_in,
                              void* d_out, int out_size) {
    static const int fsz[4] = {1605632, 802816, 401408, 200704};
    static const int rsz[4] = {62720000, 15680000, 3920000, 980000};
    static const int wsz[4] = {1280000, 2560000, 5120000, 10240000};

    const float* fmap[4] = {0, 0, 0, 0};
    const float* rfp[4]  = {0, 0, 0, 0};
    const float* wptr[4] = {0, 0, 0, 0};
    const int*   roi = 0;

    for (int i = 0; i < n_in; i++) {
        int s = in_sizes[i];
        if (s == NV) { roi = (const int*)d_in[i]; continue; }
        for (int l = 0; l < 4; l++) {
            if (s == fsz[l]) fmap[l] = (const float*)d_in[i];
            else if (s == rsz[l]) rfp[l]  = (const float*)d_in[i];
            else if (s == wsz[l]) wptr[l] = (const float*)d_in[i];
        }
    }

    float* out = (float*)d_out;

    cudaFuncSetAttribute(gemm_all, cudaFuncAttributeMaxDynamicSharedMemorySize, SMEM_TOTAL);

    split_all<<<A_ELEMS / 256, 256>>>(fmap[0], fmap[1], fmap[2], fmap[3]);          // 1
    gather_tr_all<<<dim3(132, 32), 256>>>(rfp[0], rfp[1], rfp[2], rfp[3], roi);     // 2
    gather_w_all<<<(int)(((long long)C_TOTAL * NV + 255) / 256), 256>>>(            // 3
        wptr[0], wptr[1], wptr[2], wptr[3], roi);
    gemm_all<<<3780, 256, SMEM_TOTAL>>>(out);                                        // 4 <- profiled
}